// round 9
// baseline (speedup 1.0000x reference)
#include <cuda_runtime.h>
#include <cuda_bf16.h>
#include <stdint.h>

#define DEEP_IN 200
#define MAXB 16384
#define TILE_R 128

// element strides (bf16) — identical to the R7 passing kernel
#define SX 216   // X / W1 rows (K padded 200->208)
#define SH 136   // h1 / W2 rows (K=128)

// byte offsets in dynamic smem (identical to R7)
#define XHI   0                    // X hi  [128][216]  (55296 B)
#define XLO   55296                // X lo
#define W1HI  110592               // W1 hi [128][216]
#define W1LO  165888               // W1 lo            -> total 221184
#define H1HI  0                    // h1 hi [128][136]
#define H1LO  34816                // h1 lo
#define W2HI  110592               // W2 hi [64][136]
#define W2LO  128000               // W2 lo
#define SMEM_BYTES 221184

__device__ __nv_bfloat16 g_xhi[(size_t)MAXB * DEEP_IN];
__device__ __nv_bfloat16 g_xlo[(size_t)MAXB * DEEP_IN];
__device__ float g_base[MAXB];

__device__ __forceinline__ uint32_t smem_u32(const void* p) {
    uint32_t a;
    asm("{ .reg .u64 t; cvta.to.shared.u64 t, %1; cvt.u32.u64 %0, t; }"
        : "=r"(a) : "l"(p));
    return a;
}
#define LDMX4(r, addr) \
    asm volatile("ldmatrix.sync.aligned.m8n8.x4.shared.b16 {%0,%1,%2,%3}, [%4];" \
        : "=r"((r)[0]), "=r"((r)[1]), "=r"((r)[2]), "=r"((r)[3]) : "r"(addr))
#define MMA_BF16(d, a, b0, b1) \
    asm volatile("mma.sync.aligned.m16n8k16.row.col.f32.bf16.bf16.f32 " \
        "{%0,%1,%2,%3}, {%4,%5,%6,%7}, {%8,%9}, {%0,%1,%2,%3};" \
        : "+f"((d)[0]), "+f"((d)[1]), "+f"((d)[2]), "+f"((d)[3]) \
        : "r"((a)[0]), "r"((a)[1]), "r"((a)[2]), "r"((a)[3]), "r"(b0), "r"(b1))

__device__ __forceinline__ uint32_t packbf(float v0, float v1) {
    __nv_bfloat162 p = __floats2bfloat162_rn(v0, v1);
    return *(uint32_t*)&p;
}
__device__ __forceinline__ void store_split2(char* hi, char* lo, uint32_t off,
                                             float v0, float v1) {
    __nv_bfloat16 h0 = __float2bfloat16(v0), h1 = __float2bfloat16(v1);
    float l0 = v0 - __bfloat162float(h0), l1 = v1 - __bfloat162float(h1);
    *(uint32_t*)(hi + off) = packbf(__bfloat162float(h0), __bfloat162float(h1));
    *(uint32_t*)(lo + off) = packbf(l0, l1);
}
__device__ __forceinline__ void store_split_g(__nv_bfloat16* ph, __nv_bfloat16* pl,
                                              float x) {
    __nv_bfloat16 h = __float2bfloat16(x);
    *ph = h;
    *pl = __float2bfloat16(x - __bfloat162float(h));
}

// ===========================================================================
// K1: gather + FM terms. One warp per row; 2048 CTAs -> chip-wide MLP.
// ===========================================================================
__global__ void deepfm_gather_k1(
    const int* __restrict__ uid, const int* __restrict__ iid,
    const int* __restrict__ gen, const int* __restrict__ age,
    const int* __restrict__ occ,
    const int* __restrict__ gids, const float* __restrict__ gmask,
    const float* __restrict__ dense,
    const float* __restrict__ fo_user, const float* __restrict__ fo_item,
    const float* __restrict__ fo_gender, const float* __restrict__ fo_age,
    const float* __restrict__ fo_occ, const float* __restrict__ fo_genre,
    const float* __restrict__ emb_user, const float* __restrict__ emb_item,
    const float* __restrict__ emb_gender, const float* __restrict__ emb_age,
    const float* __restrict__ emb_occ, const float* __restrict__ emb_genre,
    const float* __restrict__ dense_W, const float* __restrict__ dense_b,
    int B)
{
    const int r    = (blockIdx.x * blockDim.x + threadIdx.x) >> 5;
    const int lane = threadIdx.x & 31;
    if (r >= B) return;

    const int u  = uid[r];
    const int it = iid[r];
    const int g  = gen[r];
    const int a  = age[r];
    const int o  = occ[r];

    const float xu = emb_user  [u  * 32 + lane];
    const float xi = emb_item  [it * 32 + lane];
    const float xg = emb_gender[g  * 32 + lane];
    const float xa = emb_age   [a  * 32 + lane];
    const float xo = emb_occ   [o  * 32 + lane];

    float gsum = 0.f, msum = 0.f, fsum = 0.f;
#pragma unroll
    for (int k = 0; k < 6; k++) {
        const int   gid = gids [r * 6 + k];
        const float m   = gmask[r * 6 + k];
        gsum += m * emb_genre[gid * 32 + lane];
        msum += m;
        fsum += m * fo_genre[gid];
    }
    const float denom = fmaxf(msum, 1.0f);
    const float xge = gsum / denom;

    __nv_bfloat16* xh = g_xhi + (size_t)r * DEEP_IN;
    __nv_bfloat16* xl = g_xlo + (size_t)r * DEEP_IN;
    store_split_g(xh + lane,        xl + lane,        xu);
    store_split_g(xh + 32 + lane,   xl + 32 + lane,   xi);
    store_split_g(xh + 64 + lane,   xl + 64 + lane,   xg);
    store_split_g(xh + 96 + lane,   xl + 96 + lane,   xa);
    store_split_g(xh + 128 + lane,  xl + 128 + lane,  xo);
    store_split_g(xh + 160 + lane,  xl + 160 + lane,  xge);
    float dv = 0.f;
    if (lane < 8) {
        dv = dense[r * 8 + lane];
        store_split_g(xh + 192 + lane, xl + 192 + lane, dv);
    }

    const float s  = xu + xi + xg + xa + xo + xge;
    const float sq = xu*xu + xi*xi + xg*xg + xa*xa + xo*xo + xge*xge;
    float red = 0.5f * (s * s - sq);
    if (lane < 8) red += dv * dense_W[lane];
#pragma unroll
    for (int off = 16; off; off >>= 1)
        red += __shfl_xor_sync(0xffffffffu, red, off);
    if (lane == 0)
        g_base[r] = fo_user[u] + fo_item[it] + fo_gender[g] + fo_age[a]
                  + fo_occ[o] + fsum / denom + dense_b[0] + red;
}

// ===========================================================================
// K2: HMMA MLP — GEMM section byte-identical to the passing R7 kernel.
// Prologue = coalesced copy of X (hi/lo) from global instead of gathers.
// ===========================================================================
__global__ __launch_bounds__(512, 1) void deepfm_hmma_k2(
    const float* __restrict__ W1, const float* __restrict__ b1,
    const float* __restrict__ W2, const float* __restrict__ b2,
    const float* __restrict__ Wout, const float* __restrict__ bout,
    float* __restrict__ out, int B)
{
    extern __shared__ char sm[];
    __shared__ float base_s[TILE_R];
    __shared__ float b1s[128], b2s[64], wouts[64];
    __shared__ float part[4][128];

    const int t    = threadIdx.x;
    const int lane = t & 31;
    const int wrp  = t >> 5;
    const int rowbase = blockIdx.x * TILE_R;
    const uint32_t smb = smem_u32(sm);

    if (t < 128)      b1s[t] = b1[t];
    else if (t < 192) b2s[t - 128] = b2[t - 128];
    else if (t < 256) wouts[t - 192] = Wout[t - 192];
    if (t < TILE_R && rowbase + t < B) base_s[t] = g_base[rowbase + t];

    // ---- stage W1 (fp32 -> bf16 hi/lo), 4 threads per row (R7-identical) ---
    {
        const int j = t >> 2, q = t & 3;
        const float* src = W1 + j * DEEP_IN + q * 50;
        const uint32_t rb = j * (SX * 2) + q * 100;
#pragma unroll
        for (int s = 0; s < 25; s++) {
            const float2 v = *(const float2*)(src + s * 2);
            store_split2(sm + W1HI, sm + W1LO, rb + s * 4, v.x, v.y);
        }
    }
    // ---- zero pads k=200..207 for X and W1 (R7-identical) ------------------
    for (int e = t; e < 128 * 8; e += 512) {
        const int r = e >> 3, k = 200 + (e & 7);
        const uint32_t o = (r * SX + k) * 2;
        *(__nv_bfloat16*)(sm + XHI  + o) = __float2bfloat16(0.f);
        *(__nv_bfloat16*)(sm + XLO  + o) = __float2bfloat16(0.f);
        *(__nv_bfloat16*)(sm + W1HI + o) = __float2bfloat16(0.f);
        *(__nv_bfloat16*)(sm + W1LO + o) = __float2bfloat16(0.f);
    }
    // ---- copy X (hi/lo) from global, coalesced uint4 -----------------------
    {
        const char* gh = (const char*)g_xhi;
        const char* gl = (const char*)g_xlo;
        // 128 rows x 25 uint4 per array; row stride in smem = SX*2 = 432 B
        for (int e = t; e < 6400; e += 512) {
            const int arr = e >= 3200;
            const int i   = arr ? e - 3200 : e;
            const int row = i / 25, g4 = i % 25;
            const uint4 v = *(const uint4*)((arr ? gl : gh)
                          + (size_t)(rowbase + row) * 400 + g4 * 16);
            *(uint4*)(sm + (arr ? XLO : XHI) + row * (SX * 2) + g4 * 16) = v;
        }
    }
    __syncthreads();

    // ======================= Layer 1: 128x128x208 (R7-identical) ============
    const int wm = wrp >> 2;
    {
        const int wn = wrp & 3;
        float d[2][4][4];
#pragma unroll
        for (int r = 0; r < 2; r++)
#pragma unroll
            for (int nb = 0; nb < 4; nb++)
#pragma unroll
                for (int c = 0; c < 4; c++) d[r][nb][c] = 0.f;

        uint32_t aAddr[2], bAddr[2];
#pragma unroll
        for (int r = 0; r < 2; r++)
            aAddr[r] = smb + (uint32_t)((wm * 32 + r * 16 + (lane & 15)) * (SX * 2)
                     + (lane >> 4) * 16);
#pragma unroll
        for (int h = 0; h < 2; h++)
            bAddr[h] = smb + W1HI
                     + (uint32_t)((wn * 32 + h * 16 + ((lane >> 4) << 3) + (lane & 7)) * (SX * 2)
                     + ((lane >> 3) & 1) * 16);

        for (int ks = 0; ks < 13; ks++) {
            const uint32_t kb = ks * 32;
            uint32_t ah[2][4], al[2][4], bh[2][4], bl[2][4];
#pragma unroll
            for (int r = 0; r < 2; r++) {
                LDMX4(ah[r], aAddr[r] + XHI + kb);
                LDMX4(al[r], aAddr[r] + XLO + kb);
            }
#pragma unroll
            for (int h = 0; h < 2; h++) {
                LDMX4(bh[h], bAddr[h] + kb);
                LDMX4(bl[h], bAddr[h] + (W1LO - W1HI) + kb);
            }
#pragma unroll
            for (int r = 0; r < 2; r++)
#pragma unroll
                for (int h = 0; h < 2; h++)
#pragma unroll
                    for (int hf = 0; hf < 2; hf++) {
                        const int nb = h * 2 + hf;
                        MMA_BF16(d[r][nb], ah[r], bh[h][hf*2], bh[h][hf*2+1]);
                        MMA_BF16(d[r][nb], ah[r], bl[h][hf*2], bl[h][hf*2+1]);
                        MMA_BF16(d[r][nb], al[r], bh[h][hf*2], bh[h][hf*2+1]);
                    }
        }
        __syncthreads();

        // epilogue: relu(d + b1) -> h1 hi/lo [m][k] stride SH
#pragma unroll
        for (int r = 0; r < 2; r++)
#pragma unroll
            for (int nb = 0; nb < 4; nb++) {
                const int n = wn * 32 + nb * 8 + 2 * (lane & 3);
                const int m0 = wm * 32 + r * 16 + (lane >> 2);
                const float v0 = fmaxf(d[r][nb][0] + b1s[n], 0.f);
                const float v1 = fmaxf(d[r][nb][1] + b1s[n + 1], 0.f);
                store_split2(sm + H1HI, sm + H1LO, (m0 * SH + n) * 2, v0, v1);
                const float v2 = fmaxf(d[r][nb][2] + b1s[n], 0.f);
                const float v3 = fmaxf(d[r][nb][3] + b1s[n + 1], 0.f);
                store_split2(sm + H1HI, sm + H1LO, ((m0 + 8) * SH + n) * 2, v2, v3);
            }
    }
    // stage W2 [64][128] -> hi/lo stride SH (R7-identical)
    for (int e = t; e < 64 * 32; e += 512) {
        const int j = e >> 5, q = e & 31;
        const float4 v = *(const float4*)(W2 + j * 128 + q * 4);
        const uint32_t o = (j * SH + q * 4) * 2;
        store_split2(sm + W2HI, sm + W2LO, o,     v.x, v.y);
        store_split2(sm + W2HI, sm + W2LO, o + 4, v.z, v.w);
    }
    __syncthreads();

    // ======================= Layer 2: 128x64x128 (R7-identical) =============
    {
        const int wn2 = wrp & 3;
        float d2[2][2][4];
#pragma unroll
        for (int r = 0; r < 2; r++)
#pragma unroll
            for (int nb = 0; nb < 2; nb++)
#pragma unroll
                for (int c = 0; c < 4; c++) d2[r][nb][c] = 0.f;

        uint32_t aAddr[2];
#pragma unroll
        for (int r = 0; r < 2; r++)
            aAddr[r] = smb + (uint32_t)((wm * 32 + r * 16 + (lane & 15)) * (SH * 2)
                     + (lane >> 4) * 16);
        const uint32_t bAddr = smb + W2HI
                     + (uint32_t)((wn2 * 16 + ((lane >> 4) << 3) + (lane & 7)) * (SH * 2)
                     + ((lane >> 3) & 1) * 16);

#pragma unroll
        for (int ks = 0; ks < 8; ks++) {
            const uint32_t kb = ks * 32;
            uint32_t ah[2][4], al[2][4], bh[4], bl[4];
#pragma unroll
            for (int r = 0; r < 2; r++) {
                LDMX4(ah[r], aAddr[r] + H1HI + kb);
                LDMX4(al[r], aAddr[r] + H1LO + kb);
            }
            LDMX4(bh, bAddr + kb);
            LDMX4(bl, bAddr + (W2LO - W2HI) + kb);
#pragma unroll
            for (int r = 0; r < 2; r++)
#pragma unroll
                for (int hf = 0; hf < 2; hf++) {
                    MMA_BF16(d2[r][hf], ah[r], bh[hf*2], bh[hf*2+1]);
                    MMA_BF16(d2[r][hf], ah[r], bl[hf*2], bl[hf*2+1]);
                    MMA_BF16(d2[r][hf], al[r], bh[hf*2], bh[hf*2+1]);
                }
        }

        // epilogue 2: relu(d2 + b2) . wout, quad-reduce, partials to smem
#pragma unroll
        for (int r = 0; r < 2; r++) {
            float s_lo = 0.f, s_hi = 0.f;
#pragma unroll
            for (int nb = 0; nb < 2; nb++) {
                const int n = wn2 * 16 + nb * 8 + 2 * (lane & 3);
                s_lo += fmaxf(d2[r][nb][0] + b2s[n], 0.f)     * wouts[n]
                      + fmaxf(d2[r][nb][1] + b2s[n + 1], 0.f) * wouts[n + 1];
                s_hi += fmaxf(d2[r][nb][2] + b2s[n], 0.f)     * wouts[n]
                      + fmaxf(d2[r][nb][3] + b2s[n + 1], 0.f) * wouts[n + 1];
            }
#pragma unroll
            for (int off = 1; off <= 2; off <<= 1) {
                s_lo += __shfl_xor_sync(0xffffffffu, s_lo, off);
                s_hi += __shfl_xor_sync(0xffffffffu, s_hi, off);
            }
            if ((lane & 3) == 0) {
                const int m0 = wm * 32 + r * 16 + (lane >> 2);
                part[wn2][m0]     = s_lo;
                part[wn2][m0 + 8] = s_hi;
            }
        }
    }
    __syncthreads();

    if (t < 128) {
        const int r = rowbase + t;
        if (r < B)
            out[r] = base_s[t] + part[0][t] + part[1][t] + part[2][t] + part[3][t]
                   + bout[0];
    }
}

// ---------------------------------------------------------------------------
extern "C" void kernel_launch(void* const* d_in, const int* in_sizes, int n_in,
                              void* d_out, int out_size)
{
    const int*   uid      = (const int*)  d_in[0];
    const int*   iid      = (const int*)  d_in[1];
    const int*   gen      = (const int*)  d_in[2];
    const int*   age      = (const int*)  d_in[3];
    const int*   occ      = (const int*)  d_in[4];
    const int*   gids     = (const int*)  d_in[5];
    const float* gmask    = (const float*)d_in[6];
    const float* dense    = (const float*)d_in[7];
    const float* fo_user  = (const float*)d_in[8];
    const float* fo_item  = (const float*)d_in[9];
    const float* fo_gender= (const float*)d_in[10];
    const float* fo_age   = (const float*)d_in[11];
    const float* fo_occ   = (const float*)d_in[12];
    const float* fo_genre = (const float*)d_in[13];
    const float* emb_user = (const float*)d_in[14];
    const float* emb_item = (const float*)d_in[15];
    const float* emb_gender=(const float*)d_in[16];
    const float* emb_age  = (const float*)d_in[17];
    const float* emb_occ  = (const float*)d_in[18];
    const float* emb_genre= (const float*)d_in[19];
    const float* dense_W  = (const float*)d_in[20];
    const float* dense_b  = (const float*)d_in[21];
    const float* W1       = (const float*)d_in[22];
    const float* b1       = (const float*)d_in[23];
    const float* W2       = (const float*)d_in[24];
    const float* b2       = (const float*)d_in[25];
    const float* Wout     = (const float*)d_in[26];
    const float* bout     = (const float*)d_in[27];
    float*       out      = (float*)d_out;

    const int B = in_sizes[0];

    // K1: gather (one warp per row, wide grid)
    {
        const int threads = 256;
        const int rowsPerBlock = threads / 32;
        const int blocks = (B + rowsPerBlock - 1) / rowsPerBlock;
        deepfm_gather_k1<<<blocks, threads>>>(
            uid, iid, gen, age, occ, gids, gmask, dense,
            fo_user, fo_item, fo_gender, fo_age, fo_occ, fo_genre,
            emb_user, emb_item, emb_gender, emb_age, emb_occ, emb_genre,
            dense_W, dense_b, B);
    }
    // K2: HMMA MLP (R7 GEMM, 128 rows/CTA)
    {
        cudaFuncSetAttribute(deepfm_hmma_k2,
                             cudaFuncAttributeMaxDynamicSharedMemorySize, SMEM_BYTES);
        const int blocks = (B + TILE_R - 1) / TILE_R;
        deepfm_hmma_k2<<<blocks, 512, SMEM_BYTES>>>(
            W1, b1, W2, b2, Wout, bout, out, B);
    }
}

// round 10
// speedup vs baseline: 1.0944x; 1.0944x over previous
#include <cuda_runtime.h>
#include <cuda_bf16.h>
#include <stdint.h>

#define DEEP_IN 200
#define MAXB 16384
#define TILE_R 64

// ---------------- K2 dynamic smem layout (bytes) ---------------------------
// X  tile: [64 r][216 k] bf16, row stride 432 B (conflict-free ldmatrix)
// W1 chunk: [128 j][104 k] bf16, row stride 208 B
// h1 (reuses X region): [64 m][136 k] stride 272 B
// W2 (reuses W1 region): [64 j][136 k] stride 272 B
#define XHI   0
#define XLO   27648
#define WCHI  55296
#define WCLO  81920
#define DSM   108544
#define H1HI  0
#define H1LO  17408
#define W2HI  55296
#define W2LO  72704

__device__ __nv_bfloat16 g_xhi[(size_t)MAXB * DEEP_IN];
__device__ __nv_bfloat16 g_xlo[(size_t)MAXB * DEEP_IN];
__device__ float g_base[MAXB];

__device__ __forceinline__ uint32_t smem_u32(const void* p) {
    uint32_t a;
    asm("{ .reg .u64 t; cvta.to.shared.u64 t, %1; cvt.u32.u64 %0, t; }"
        : "=r"(a) : "l"(p));
    return a;
}
#define LDMX4(r, addr) \
    asm volatile("ldmatrix.sync.aligned.m8n8.x4.shared.b16 {%0,%1,%2,%3}, [%4];" \
        : "=r"((r)[0]), "=r"((r)[1]), "=r"((r)[2]), "=r"((r)[3]) : "r"(addr))
#define MMA_BF16(d, a, b0, b1) \
    asm volatile("mma.sync.aligned.m16n8k16.row.col.f32.bf16.bf16.f32 " \
        "{%0,%1,%2,%3}, {%4,%5,%6,%7}, {%8,%9}, {%0,%1,%2,%3};" \
        : "+f"((d)[0]), "+f"((d)[1]), "+f"((d)[2]), "+f"((d)[3]) \
        : "r"((a)[0]), "r"((a)[1]), "r"((a)[2]), "r"((a)[3]), "r"(b0), "r"(b1))

__device__ __forceinline__ uint32_t packbf(float v0, float v1) {
    __nv_bfloat162 p = __floats2bfloat162_rn(v0, v1);
    return *(uint32_t*)&p;
}
__device__ __forceinline__ void store_split2(char* hi, char* lo, uint32_t off,
                                             float v0, float v1) {
    __nv_bfloat16 h0 = __float2bfloat16(v0), h1 = __float2bfloat16(v1);
    float l0 = v0 - __bfloat162float(h0), l1 = v1 - __bfloat162float(h1);
    *(uint32_t*)(hi + off) = packbf(__bfloat162float(h0), __bfloat162float(h1));
    *(uint32_t*)(lo + off) = packbf(l0, l1);
}
__device__ __forceinline__ void store_split_g(__nv_bfloat16* ph, __nv_bfloat16* pl,
                                              float x) {
    __nv_bfloat16 h = __float2bfloat16(x);
    *ph = h;
    *pl = __float2bfloat16(x - __bfloat162float(h));
}

// ===========================================================================
// K1: gather + FM terms. One warp per row (unchanged from passing R9).
// ===========================================================================
__global__ void deepfm_gather_k1(
    const int* __restrict__ uid, const int* __restrict__ iid,
    const int* __restrict__ gen, const int* __restrict__ age,
    const int* __restrict__ occ,
    const int* __restrict__ gids, const float* __restrict__ gmask,
    const float* __restrict__ dense,
    const float* __restrict__ fo_user, const float* __restrict__ fo_item,
    const float* __restrict__ fo_gender, const float* __restrict__ fo_age,
    const float* __restrict__ fo_occ, const float* __restrict__ fo_genre,
    const float* __restrict__ emb_user, const float* __restrict__ emb_item,
    const float* __restrict__ emb_gender, const float* __restrict__ emb_age,
    const float* __restrict__ emb_occ, const float* __restrict__ emb_genre,
    const float* __restrict__ dense_W, const float* __restrict__ dense_b,
    int B)
{
    const int r    = (blockIdx.x * blockDim.x + threadIdx.x) >> 5;
    const int lane = threadIdx.x & 31;
    if (r >= B) return;

    const int u  = uid[r];
    const int it = iid[r];
    const int g  = gen[r];
    const int a  = age[r];
    const int o  = occ[r];

    const float xu = emb_user  [u  * 32 + lane];
    const float xi = emb_item  [it * 32 + lane];
    const float xg = emb_gender[g  * 32 + lane];
    const float xa = emb_age   [a  * 32 + lane];
    const float xo = emb_occ   [o  * 32 + lane];

    float gsum = 0.f, msum = 0.f, fsum = 0.f;
#pragma unroll
    for (int k = 0; k < 6; k++) {
        const int   gid = gids [r * 6 + k];
        const float m   = gmask[r * 6 + k];
        gsum += m * emb_genre[gid * 32 + lane];
        msum += m;
        fsum += m * fo_genre[gid];
    }
    const float denom = fmaxf(msum, 1.0f);
    const float xge = gsum / denom;

    __nv_bfloat16* xh = g_xhi + (size_t)r * DEEP_IN;
    __nv_bfloat16* xl = g_xlo + (size_t)r * DEEP_IN;
    store_split_g(xh + lane,        xl + lane,        xu);
    store_split_g(xh + 32 + lane,   xl + 32 + lane,   xi);
    store_split_g(xh + 64 + lane,   xl + 64 + lane,   xg);
    store_split_g(xh + 96 + lane,   xl + 96 + lane,   xa);
    store_split_g(xh + 128 + lane,  xl + 128 + lane,  xo);
    store_split_g(xh + 160 + lane,  xl + 160 + lane,  xge);
    float dv = 0.f;
    if (lane < 8) {
        dv = dense[r * 8 + lane];
        store_split_g(xh + 192 + lane, xl + 192 + lane, dv);
    }

    const float s  = xu + xi + xg + xa + xo + xge;
    const float sq = xu*xu + xi*xi + xg*xg + xa*xa + xo*xo + xge*xge;
    float red = 0.5f * (s * s - sq);
    if (lane < 8) red += dv * dense_W[lane];
#pragma unroll
    for (int off = 16; off; off >>= 1)
        red += __shfl_xor_sync(0xffffffffu, red, off);
    if (lane == 0)
        g_base[r] = fo_user[u] + fo_item[it] + fo_gender[g] + fo_age[a]
                  + fo_occ[o] + fsum / denom + dense_b[0] + red;
}

// W1 chunk staging: full 104-elem rows, pads and k>=200 zeroed.
__device__ __forceinline__ void stage_w1_chunk(char* sm, const float* __restrict__ W1,
                                               int kbase, int t)
{
    for (int e = t; e < 128 * 52; e += 256) {
        const int j = e / 52, p = e % 52;
        float v0 = 0.f, v1 = 0.f;
        if (p < 48) {
            const int kg = kbase + p * 2;
            if (kg < DEEP_IN) {
                const float2 v = *(const float2*)(W1 + j * DEEP_IN + kg);
                v0 = v.x; v1 = v.y;
            }
        }
        store_split2(sm + WCHI, sm + WCLO, j * 208 + p * 4, v0, v1);
    }
}

// ===========================================================================
// K2: HMMA MLP, 64 rows/CTA, 256 threads, 2 CTAs/SM.
// W1 in 3 K-chunks: 96 + 96 + 16 (chunk 2 = ONE k-step; no smem overreads).
// ===========================================================================
__global__ __launch_bounds__(256, 2) void deepfm_mlp_k2(
    const float* __restrict__ W1, const float* __restrict__ b1,
    const float* __restrict__ W2, const float* __restrict__ b2,
    const float* __restrict__ Wout, const float* __restrict__ bout,
    float* __restrict__ out, int B)
{
    extern __shared__ char sm[];
    __shared__ float base_s[TILE_R];
    __shared__ float b1s[128], b2s[64], wouts[64];
    __shared__ float part[4][TILE_R];

    const int t    = threadIdx.x;
    const int lane = t & 31;
    const int wrp  = t >> 5;        // 0..7
    const int wm   = wrp >> 2;      // 0..1 (32 rows each)
    const int rowbase = blockIdx.x * TILE_R;
    const uint32_t smb = smem_u32(sm);

    if (t < 128)      b1s[t] = b1[t];
    else if (t < 192) b2s[t - 128] = b2[t - 128];
    else              wouts[t - 192] = Wout[t - 192];
    if (t < TILE_R && rowbase + t < B) base_s[t] = g_base[rowbase + t];

    // ---- load X tile (hi/lo) coalesced: 64 rows x 25 uint4 per array -------
    {
        const char* gh = (const char*)g_xhi;
        const char* gl = (const char*)g_xlo;
        for (int e = t; e < 3200; e += 256) {
            const int arr = e >= 1600;
            const int i   = arr ? e - 1600 : e;
            const int row = i / 25, g4 = i % 25;
            const uint4 v = *(const uint4*)((arr ? gl : gh)
                          + (size_t)(rowbase + row) * 400 + g4 * 16);
            *(uint4*)(sm + (arr ? XLO : XHI) + row * 432 + g4 * 16) = v;
        }
        // zero pads k = 200..215 (bytes 400..431 of each 432-B row — FULL row)
        for (int e = t; e < TILE_R * 16; e += 256) {
            const int r = e >> 4, k = 200 + (e & 15);
            *(__nv_bfloat16*)(sm + XHI + r * 432 + k * 2) = __float2bfloat16(0.f);
            *(__nv_bfloat16*)(sm + XLO + r * 432 + k * 2) = __float2bfloat16(0.f);
        }
    }
    // ---- stage W1 chunk 0 (k 0..95) ----------------------------------------
    stage_w1_chunk(sm, W1, 0, t);
    __syncthreads();

    // ---- Layer 1: 64x128x200, 3 K-chunks, accumulators persist -------------
    const int wn = wrp & 3;
    float d[2][4][4];
#pragma unroll
    for (int r = 0; r < 2; r++)
#pragma unroll
        for (int nb = 0; nb < 4; nb++)
#pragma unroll
            for (int c = 0; c < 4; c++) d[r][nb][c] = 0.f;

    uint32_t aAddr[2], bAddr[2];
#pragma unroll
    for (int r = 0; r < 2; r++)
        aAddr[r] = smb + (uint32_t)((wm * 32 + r * 16 + (lane & 15)) * 432
                 + (lane >> 4) * 16);
#pragma unroll
    for (int h = 0; h < 2; h++)
        bAddr[h] = smb + WCHI
                 + (uint32_t)((wn * 32 + h * 16 + ((lane >> 4) << 3) + (lane & 7)) * 208
                 + ((lane >> 3) & 1) * 16);

    for (int c = 0; c < 2; c++) {
#pragma unroll
        for (int ks = 0; ks < 6; ks++) {
            const uint32_t kbA = c * 192 + ks * 32;   // chunk c covers elems 96c..96c+95
            const uint32_t kbB = ks * 32;
            uint32_t ah[2][4], al[2][4], bh[2][4], bl[2][4];
#pragma unroll
            for (int r = 0; r < 2; r++) {
                LDMX4(ah[r], aAddr[r] + XHI + kbA);
                LDMX4(al[r], aAddr[r] + (XLO - XHI) + kbA);
            }
#pragma unroll
            for (int h = 0; h < 2; h++) {
                LDMX4(bh[h], bAddr[h] + kbB);
                LDMX4(bl[h], bAddr[h] + (WCLO - WCHI) + kbB);
            }
#pragma unroll
            for (int r = 0; r < 2; r++)
#pragma unroll
                for (int h = 0; h < 2; h++)
#pragma unroll
                    for (int hf = 0; hf < 2; hf++) {
                        const int nb = h * 2 + hf;
                        MMA_BF16(d[r][nb], ah[r], bh[h][hf*2], bh[h][hf*2+1]);
                        MMA_BF16(d[r][nb], ah[r], bl[h][hf*2], bl[h][hf*2+1]);
                        MMA_BF16(d[r][nb], al[r], bh[h][hf*2], bh[h][hf*2+1]);
                    }
        }
        __syncthreads();                       // chunk reads done
        stage_w1_chunk(sm, W1, (c + 1) * 96, t);
        __syncthreads();
    }
    // ---- chunk 2: elems 192..207 — exactly ONE k-step (no overreads) -------
    {
        const uint32_t kbA = 384;              // elem 192 (bytes)
        uint32_t ah[2][4], al[2][4], bh[2][4], bl[2][4];
#pragma unroll
        for (int r = 0; r < 2; r++) {
            LDMX4(ah[r], aAddr[r] + XHI + kbA);
            LDMX4(al[r], aAddr[r] + (XLO - XHI) + kbA);
        }
#pragma unroll
        for (int h = 0; h < 2; h++) {
            LDMX4(bh[h], bAddr[h]);
            LDMX4(bl[h], bAddr[h] + (WCLO - WCHI));
        }
#pragma unroll
        for (int r = 0; r < 2; r++)
#pragma unroll
            for (int h = 0; h < 2; h++)
#pragma unroll
                for (int hf = 0; hf < 2; hf++) {
                    const int nb = h * 2 + hf;
                    MMA_BF16(d[r][nb], ah[r], bh[h][hf*2], bh[h][hf*2+1]);
                    MMA_BF16(d[r][nb], ah[r], bl[h][hf*2], bl[h][hf*2+1]);
                    MMA_BF16(d[r][nb], al[r], bh[h][hf*2], bh[h][hf*2+1]);
                }
        __syncthreads();
    }

    // ---- h1 epilogue: relu(d + b1) -> hi/lo [m][k] stride 272 --------------
    {
#pragma unroll
        for (int r = 0; r < 2; r++)
#pragma unroll
            for (int nb = 0; nb < 4; nb++) {
                const int n = wn * 32 + nb * 8 + 2 * (lane & 3);
                const int m0 = wm * 32 + r * 16 + (lane >> 2);
                const float v0 = fmaxf(d[r][nb][0] + b1s[n], 0.f);
                const float v1 = fmaxf(d[r][nb][1] + b1s[n + 1], 0.f);
                store_split2(sm + H1HI, sm + H1LO, m0 * 272 + n * 2, v0, v1);
                const float v2 = fmaxf(d[r][nb][2] + b1s[n], 0.f);
                const float v3 = fmaxf(d[r][nb][3] + b1s[n + 1], 0.f);
                store_split2(sm + H1HI, sm + H1LO, (m0 + 8) * 272 + n * 2, v2, v3);
            }
    }
    // stage W2 [64][128] -> hi/lo stride 272 (reuses W1 chunk region)
    for (int e = t; e < 64 * 32; e += 256) {
        const int j = e >> 5, q = e & 31;
        const float4 v = *(const float4*)(W2 + j * 128 + q * 4);
        const uint32_t o = j * 272 + q * 8;
        store_split2(sm + W2HI, sm + W2LO, o,     v.x, v.y);
        store_split2(sm + W2HI, sm + W2LO, o + 4, v.z, v.w);
    }
    __syncthreads();

    // ---- Layer 2: 64x64x128 ------------------------------------------------
    {
        const int wn2 = wrp & 3;                // 16 cols each
        float d2[2][2][4];
#pragma unroll
        for (int r = 0; r < 2; r++)
#pragma unroll
            for (int nb = 0; nb < 2; nb++)
#pragma unroll
                for (int c = 0; c < 4; c++) d2[r][nb][c] = 0.f;

        uint32_t a2[2];
#pragma unroll
        for (int r = 0; r < 2; r++)
            a2[r] = smb + (uint32_t)((wm * 32 + r * 16 + (lane & 15)) * 272
                  + (lane >> 4) * 16);
        const uint32_t b2a = smb + W2HI
                  + (uint32_t)((wn2 * 16 + ((lane >> 4) << 3) + (lane & 7)) * 272
                  + ((lane >> 3) & 1) * 16);

#pragma unroll
        for (int ks = 0; ks < 8; ks++) {
            const uint32_t kb = ks * 32;
            uint32_t ah[2][4], al[2][4], bh[4], bl[4];
#pragma unroll
            for (int r = 0; r < 2; r++) {
                LDMX4(ah[r], a2[r] + H1HI + kb);
                LDMX4(al[r], a2[r] + (H1LO - H1HI) + kb);
            }
            LDMX4(bh, b2a + kb);
            LDMX4(bl, b2a + (W2LO - W2HI) + kb);
#pragma unroll
            for (int r = 0; r < 2; r++)
#pragma unroll
                for (int hf = 0; hf < 2; hf++) {
                    MMA_BF16(d2[r][hf], ah[r], bh[hf*2], bh[hf*2+1]);
                    MMA_BF16(d2[r][hf], ah[r], bl[hf*2], bl[hf*2+1]);
                    MMA_BF16(d2[r][hf], al[r], bh[hf*2], bh[hf*2+1]);
                }
        }

        // epilogue 2
#pragma unroll
        for (int r = 0; r < 2; r++) {
            float s_lo = 0.f, s_hi = 0.f;
#pragma unroll
            for (int nb = 0; nb < 2; nb++) {
                const int n = wn2 * 16 + nb * 8 + 2 * (lane & 3);
                s_lo += fmaxf(d2[r][nb][0] + b2s[n], 0.f)     * wouts[n]
                      + fmaxf(d2[r][nb][1] + b2s[n + 1], 0.f) * wouts[n + 1];
                s_hi += fmaxf(d2[r][nb][2] + b2s[n], 0.f)     * wouts[n]
                      + fmaxf(d2[r][nb][3] + b2s[n + 1], 0.f) * wouts[n + 1];
            }
#pragma unroll
            for (int off = 1; off <= 2; off <<= 1) {
                s_lo += __shfl_xor_sync(0xffffffffu, s_lo, off);
                s_hi += __shfl_xor_sync(0xffffffffu, s_hi, off);
            }
            if ((lane & 3) == 0) {
                const int m0 = wm * 32 + r * 16 + (lane >> 2);
                part[wn2][m0]     = s_lo;
                part[wn2][m0 + 8] = s_hi;
            }
        }
    }
    __syncthreads();

    if (t < TILE_R) {
        const int r = rowbase + t;
        if (r < B)
            out[r] = base_s[t] + part[0][t] + part[1][t] + part[2][t] + part[3][t]
                   + bout[0];
    }
}

// ---------------------------------------------------------------------------
extern "C" void kernel_launch(void* const* d_in, const int* in_sizes, int n_in,
                              void* d_out, int out_size)
{
    const int*   uid      = (const int*)  d_in[0];
    const int*   iid      = (const int*)  d_in[1];
    const int*   gen      = (const int*)  d_in[2];
    const int*   age      = (const int*)  d_in[3];
    const int*   occ      = (const int*)  d_in[4];
    const int*   gids     = (const int*)  d_in[5];
    const float* gmask    = (const float*)d_in[6];
    const float* dense    = (const float*)d_in[7];
    const float* fo_user  = (const float*)d_in[8];
    const float* fo_item  = (const float*)d_in[9];
    const float* fo_gender= (const float*)d_in[10];
    const float* fo_age   = (const float*)d_in[11];
    const float* fo_occ   = (const float*)d_in[12];
    const float* fo_genre = (const float*)d_in[13];
    const float* emb_user = (const float*)d_in[14];
    const float* emb_item = (const float*)d_in[15];
    const float* emb_gender=(const float*)d_in[16];
    const float* emb_age  = (const float*)d_in[17];
    const float* emb_occ  = (const float*)d_in[18];
    const float* emb_genre= (const float*)d_in[19];
    const float* dense_W  = (const float*)d_in[20];
    const float* dense_b  = (const float*)d_in[21];
    const float* W1       = (const float*)d_in[22];
    const float* b1       = (const float*)d_in[23];
    const float* W2       = (const float*)d_in[24];
    const float* b2       = (const float*)d_in[25];
    const float* Wout     = (const float*)d_in[26];
    const float* bout     = (const float*)d_in[27];
    float*       out      = (float*)d_out;

    const int B = in_sizes[0];

    // K1: gather (one warp per row, wide grid)
    {
        const int threads = 256;
        const int rowsPerBlock = threads / 32;
        const int blocks = (B + rowsPerBlock - 1) / rowsPerBlock;
        deepfm_gather_k1<<<blocks, threads>>>(
            uid, iid, gen, age, occ, gids, gmask, dense,
            fo_user, fo_item, fo_gender, fo_age, fo_occ, fo_genre,
            emb_user, emb_item, emb_gender, emb_age, emb_occ, emb_genre,
            dense_W, dense_b, B);
    }
    // K2: HMMA MLP (64 rows/CTA, 2 CTAs/SM)
    {
        cudaFuncSetAttribute(deepfm_mlp_k2,
                             cudaFuncAttributeMaxDynamicSharedMemorySize, DSM);
        const int blocks = (B + TILE_R - 1) / TILE_R;
        deepfm_mlp_k2<<<blocks, 256, DSM>>>(W1, b1, W2, b2, Wout, bout, out, B);
    }
}

// round 11
// speedup vs baseline: 1.1793x; 1.0775x over previous
#include <cuda_runtime.h>
#include <cuda_bf16.h>
#include <stdint.h>

#define DEEP_IN 200
#define MAXB 16384
#define TILE_R 64
#define XROW 216              // padded X row (elems); 432 B

// ---------------- K2 dynamic smem layout (bytes) — identical to R10 --------
#define XHI   0
#define XLO   27648
#define WCHI  55296
#define WCLO  81920
#define DSM   108544
#define H1HI  0
#define H1LO  17408
#define W2HI  55296
#define W2LO  72704

// pre-split weight/activation buffers (exact smem layouts)
__device__ __nv_bfloat16 g_xhi[(size_t)MAXB * XROW];
__device__ __nv_bfloat16 g_xlo[(size_t)MAXB * XROW];
__device__ __nv_bfloat16 g_w1chi[3 * 128 * 104];   // per-chunk layout, pads zeroed
__device__ __nv_bfloat16 g_w1clo[3 * 128 * 104];
__device__ __nv_bfloat16 g_w2hi[64 * 136];
__device__ __nv_bfloat16 g_w2lo[64 * 136];
__device__ float g_base[MAXB];

__device__ __forceinline__ uint32_t smem_u32(const void* p) {
    uint32_t a;
    asm("{ .reg .u64 t; cvta.to.shared.u64 t, %1; cvt.u32.u64 %0, t; }"
        : "=r"(a) : "l"(p));
    return a;
}
#define LDMX4(r, addr) \
    asm volatile("ldmatrix.sync.aligned.m8n8.x4.shared.b16 {%0,%1,%2,%3}, [%4];" \
        : "=r"((r)[0]), "=r"((r)[1]), "=r"((r)[2]), "=r"((r)[3]) : "r"(addr))
#define MMA_BF16(d, a, b0, b1) \
    asm volatile("mma.sync.aligned.m16n8k16.row.col.f32.bf16.bf16.f32 " \
        "{%0,%1,%2,%3}, {%4,%5,%6,%7}, {%8,%9}, {%0,%1,%2,%3};" \
        : "+f"((d)[0]), "+f"((d)[1]), "+f"((d)[2]), "+f"((d)[3]) \
        : "r"((a)[0]), "r"((a)[1]), "r"((a)[2]), "r"((a)[3]), "r"(b0), "r"(b1))

__device__ __forceinline__ uint32_t packbf(float v0, float v1) {
    __nv_bfloat162 p = __floats2bfloat162_rn(v0, v1);
    return *(uint32_t*)&p;
}
__device__ __forceinline__ void store_split2(char* hi, char* lo, uint32_t off,
                                             float v0, float v1) {
    __nv_bfloat16 h0 = __float2bfloat16(v0), h1 = __float2bfloat16(v1);
    float l0 = v0 - __bfloat162float(h0), l1 = v1 - __bfloat162float(h1);
    *(uint32_t*)(hi + off) = packbf(__bfloat162float(h0), __bfloat162float(h1));
    *(uint32_t*)(lo + off) = packbf(l0, l1);
}
__device__ __forceinline__ void store_split_g(__nv_bfloat16* ph, __nv_bfloat16* pl,
                                              float x) {
    __nv_bfloat16 h = __float2bfloat16(x);
    *ph = h;
    *pl = __float2bfloat16(x - __bfloat162float(h));
}

// ===========================================================================
// K1: gather + FM terms (one warp per row) + weight pre-split (96 extra blocks)
// ===========================================================================
__global__ void deepfm_gather_k1(
    const int* __restrict__ uid, const int* __restrict__ iid,
    const int* __restrict__ gen, const int* __restrict__ age,
    const int* __restrict__ occ,
    const int* __restrict__ gids, const float* __restrict__ gmask,
    const float* __restrict__ dense,
    const float* __restrict__ fo_user, const float* __restrict__ fo_item,
    const float* __restrict__ fo_gender, const float* __restrict__ fo_age,
    const float* __restrict__ fo_occ, const float* __restrict__ fo_genre,
    const float* __restrict__ emb_user, const float* __restrict__ emb_item,
    const float* __restrict__ emb_gender, const float* __restrict__ emb_age,
    const float* __restrict__ emb_occ, const float* __restrict__ emb_genre,
    const float* __restrict__ dense_W, const float* __restrict__ dense_b,
    const float* __restrict__ W1, const float* __restrict__ W2,
    int B, int nb1)
{
    if ((int)blockIdx.x >= nb1) {
        // ---- weight prep: split W1/W2 into exact smem layouts -------------
        const int gid = (blockIdx.x - nb1) * blockDim.x + threadIdx.x;
        if (gid < 3 * 128 * 52) {
            const int c = gid / (128 * 52);
            const int rem = gid % (128 * 52);
            const int j = rem / 52, p = rem % 52;
            const int kg = c * 96 + p * 2;
            float v0 = 0.f, v1 = 0.f;
            if (p < 48 && kg < DEEP_IN) {
                const float2 v = *(const float2*)(W1 + j * DEEP_IN + kg);
                v0 = v.x; v1 = v.y;
            }
            const int o = (c * 128 + j) * 104 + p * 2;
            store_split_g(g_w1chi + o,     g_w1clo + o,     v0);
            store_split_g(g_w1chi + o + 1, g_w1clo + o + 1, v1);
        } else if (gid < 3 * 128 * 52 + 64 * 68) {
            const int idx = gid - 3 * 128 * 52;
            const int j = idx / 68, p = idx % 68;
            const int k = p * 2;
            float v0 = 0.f, v1 = 0.f;
            if (k < 128) {
                const float2 v = *(const float2*)(W2 + j * 128 + k);
                v0 = v.x; v1 = v.y;
            }
            const int o = j * 136 + k;
            store_split_g(g_w2hi + o,     g_w2lo + o,     v0);
            store_split_g(g_w2hi + o + 1, g_w2lo + o + 1, v1);
        }
        return;
    }

    const int r    = (blockIdx.x * blockDim.x + threadIdx.x) >> 5;
    const int lane = threadIdx.x & 31;
    if (r >= B) return;

    const int u  = uid[r];
    const int it = iid[r];
    const int g  = gen[r];
    const int a  = age[r];
    const int o  = occ[r];

    const float xu = emb_user  [u  * 32 + lane];
    const float xi = emb_item  [it * 32 + lane];
    const float xg = emb_gender[g  * 32 + lane];
    const float xa = emb_age   [a  * 32 + lane];
    const float xo = emb_occ   [o  * 32 + lane];

    float gsum = 0.f, msum = 0.f, fsum = 0.f;
#pragma unroll
    for (int k = 0; k < 6; k++) {
        const int   gid = gids [r * 6 + k];
        const float m   = gmask[r * 6 + k];
        gsum += m * emb_genre[gid * 32 + lane];
        msum += m;
        fsum += m * fo_genre[gid];
    }
    const float denom = fmaxf(msum, 1.0f);
    const float xge = gsum / denom;

    __nv_bfloat16* xh = g_xhi + (size_t)r * XROW;
    __nv_bfloat16* xl = g_xlo + (size_t)r * XROW;
    store_split_g(xh + lane,        xl + lane,        xu);
    store_split_g(xh + 32 + lane,   xl + 32 + lane,   xi);
    store_split_g(xh + 64 + lane,   xl + 64 + lane,   xg);
    store_split_g(xh + 96 + lane,   xl + 96 + lane,   xa);
    store_split_g(xh + 128 + lane,  xl + 128 + lane,  xo);
    store_split_g(xh + 160 + lane,  xl + 160 + lane,  xge);
    float dv = 0.f;
    if (lane < 8) {
        dv = dense[r * 8 + lane];
        store_split_g(xh + 192 + lane, xl + 192 + lane, dv);
    }
    if (lane < 16) {   // zero pads k = 200..215
        xh[200 + lane] = __float2bfloat16(0.f);
        xl[200 + lane] = __float2bfloat16(0.f);
    }

    const float s  = xu + xi + xg + xa + xo + xge;
    const float sq = xu*xu + xi*xi + xg*xg + xa*xa + xo*xo + xge*xge;
    float red = 0.5f * (s * s - sq);
    if (lane < 8) red += dv * dense_W[lane];
#pragma unroll
    for (int off = 16; off; off >>= 1)
        red += __shfl_xor_sync(0xffffffffu, red, off);
    if (lane == 0)
        g_base[r] = fo_user[u] + fo_item[it] + fo_gender[g] + fo_age[a]
                  + fo_occ[o] + fsum / denom + dense_b[0] + red;
}

// ===========================================================================
// K2: HMMA MLP, 64 rows/CTA, 256 threads, 2 CTAs/SM.
// All staging = pure linear uint4 copies (layouts pre-matched in global).
// ===========================================================================
__global__ __launch_bounds__(256, 2) void deepfm_mlp_k2(
    const float* __restrict__ b1, const float* __restrict__ b2,
    const float* __restrict__ Wout, const float* __restrict__ bout,
    float* __restrict__ out, int B)
{
    extern __shared__ char sm[];
    __shared__ float base_s[TILE_R];
    __shared__ float b1s[128], b2s[64], wouts[64];
    __shared__ float part[4][TILE_R];

    const int t    = threadIdx.x;
    const int lane = t & 31;
    const int wrp  = t >> 5;        // 0..7
    const int wm   = wrp >> 2;      // 0..1 (32 rows each)
    const int rowbase = blockIdx.x * TILE_R;
    const uint32_t smb = smem_u32(sm);

    if (t < 128)      b1s[t] = b1[t];
    else if (t < 192) b2s[t - 128] = b2[t - 128];
    else              wouts[t - 192] = Wout[t - 192];
    if (t < TILE_R && rowbase + t < B) base_s[t] = g_base[rowbase + t];

    // ---- X tile: pure linear copy, 64 rows x 432 B, hi + lo ---------------
    {
        const char* gh = (const char*)g_xhi + (size_t)rowbase * 432;
        const char* gl = (const char*)g_xlo + (size_t)rowbase * 432;
        for (int e = t; e < 2 * 1728; e += 256) {
            const int arr = e >= 1728;
            const int i   = arr ? e - 1728 : e;
            *(uint4*)(sm + (arr ? XLO : XHI) + i * 16)
                = *(const uint4*)((arr ? gl : gh) + i * 16);
        }
    }
    // ---- W1 chunk 0: pure linear copy (26624 B per buffer) -----------------
    {
        const char* gh = (const char*)g_w1chi;
        const char* gl = (const char*)g_w1clo;
        for (int e = t; e < 2 * 1664; e += 256) {
            const int arr = e >= 1664;
            const int i   = arr ? e - 1664 : e;
            *(uint4*)(sm + (arr ? WCLO : WCHI) + i * 16)
                = *(const uint4*)((arr ? gl : gh) + i * 16);
        }
    }
    __syncthreads();

    // ---- Layer 1: 64x128x200, 3 K-chunks (96+96+16), accumulators persist --
    const int wn = wrp & 3;
    float d[2][4][4];
#pragma unroll
    for (int r = 0; r < 2; r++)
#pragma unroll
        for (int nb = 0; nb < 4; nb++)
#pragma unroll
            for (int c = 0; c < 4; c++) d[r][nb][c] = 0.f;

    uint32_t aAddr[2], bAddr[2];
#pragma unroll
    for (int r = 0; r < 2; r++)
        aAddr[r] = smb + (uint32_t)((wm * 32 + r * 16 + (lane & 15)) * 432
                 + (lane >> 4) * 16);
#pragma unroll
    for (int h = 0; h < 2; h++)
        bAddr[h] = smb + WCHI
                 + (uint32_t)((wn * 32 + h * 16 + ((lane >> 4) << 3) + (lane & 7)) * 208
                 + ((lane >> 3) & 1) * 16);

    for (int c = 0; c < 2; c++) {
#pragma unroll
        for (int ks = 0; ks < 6; ks++) {
            const uint32_t kbA = c * 192 + ks * 32;
            const uint32_t kbB = ks * 32;
            uint32_t ah[2][4], al[2][4], bh[2][4], bl[2][4];
#pragma unroll
            for (int r = 0; r < 2; r++) {
                LDMX4(ah[r], aAddr[r] + XHI + kbA);
                LDMX4(al[r], aAddr[r] + (XLO - XHI) + kbA);
            }
#pragma unroll
            for (int h = 0; h < 2; h++) {
                LDMX4(bh[h], bAddr[h] + kbB);
                LDMX4(bl[h], bAddr[h] + (WCLO - WCHI) + kbB);
            }
#pragma unroll
            for (int r = 0; r < 2; r++)
#pragma unroll
                for (int h = 0; h < 2; h++)
#pragma unroll
                    for (int hf = 0; hf < 2; hf++) {
                        const int nb = h * 2 + hf;
                        MMA_BF16(d[r][nb], ah[r], bh[h][hf*2], bh[h][hf*2+1]);
                        MMA_BF16(d[r][nb], ah[r], bl[h][hf*2], bl[h][hf*2+1]);
                        MMA_BF16(d[r][nb], al[r], bh[h][hf*2], bh[h][hf*2+1]);
                    }
        }
        __syncthreads();
        // stage next W1 chunk (pure copy)
        {
            const char* gh = (const char*)g_w1chi + (c + 1) * 26624;
            const char* gl = (const char*)g_w1clo + (c + 1) * 26624;
            for (int e = t; e < 2 * 1664; e += 256) {
                const int arr = e >= 1664;
                const int i   = arr ? e - 1664 : e;
                *(uint4*)(sm + (arr ? WCLO : WCHI) + i * 16)
                    = *(const uint4*)((arr ? gl : gh) + i * 16);
            }
        }
        __syncthreads();
    }
    // ---- chunk 2: elems 192..207 — exactly ONE k-step ----------------------
    {
        const uint32_t kbA = 384;
        uint32_t ah[2][4], al[2][4], bh[2][4], bl[2][4];
#pragma unroll
        for (int r = 0; r < 2; r++) {
            LDMX4(ah[r], aAddr[r] + XHI + kbA);
            LDMX4(al[r], aAddr[r] + (XLO - XHI) + kbA);
        }
#pragma unroll
        for (int h = 0; h < 2; h++) {
            LDMX4(bh[h], bAddr[h]);
            LDMX4(bl[h], bAddr[h] + (WCLO - WCHI));
        }
#pragma unroll
        for (int r = 0; r < 2; r++)
#pragma unroll
            for (int h = 0; h < 2; h++)
#pragma unroll
                for (int hf = 0; hf < 2; hf++) {
                    const int nb = h * 2 + hf;
                    MMA_BF16(d[r][nb], ah[r], bh[h][hf*2], bh[h][hf*2+1]);
                    MMA_BF16(d[r][nb], ah[r], bl[h][hf*2], bl[h][hf*2+1]);
                    MMA_BF16(d[r][nb], al[r], bh[h][hf*2], bh[h][hf*2+1]);
                }
        __syncthreads();
    }

    // ---- h1 epilogue: relu(d + b1) -> hi/lo [m][k] stride 272 --------------
    {
#pragma unroll
        for (int r = 0; r < 2; r++)
#pragma unroll
            for (int nb = 0; nb < 4; nb++) {
                const int n = wn * 32 + nb * 8 + 2 * (lane & 3);
                const int m0 = wm * 32 + r * 16 + (lane >> 2);
                const float v0 = fmaxf(d[r][nb][0] + b1s[n], 0.f);
                const float v1 = fmaxf(d[r][nb][1] + b1s[n + 1], 0.f);
                store_split2(sm + H1HI, sm + H1LO, m0 * 272 + n * 2, v0, v1);
                const float v2 = fmaxf(d[r][nb][2] + b1s[n], 0.f);
                const float v3 = fmaxf(d[r][nb][3] + b1s[n + 1], 0.f);
                store_split2(sm + H1HI, sm + H1LO, (m0 + 8) * 272 + n * 2, v2, v3);
            }
    }
    // stage W2: pure linear copy (17408 B per buffer)
    {
        const char* gh = (const char*)g_w2hi;
        const char* gl = (const char*)g_w2lo;
        for (int e = t; e < 2 * 1088; e += 256) {
            const int arr = e >= 1088;
            const int i   = arr ? e - 1088 : e;
            *(uint4*)(sm + (arr ? W2LO : W2HI) + i * 16)
                = *(const uint4*)((arr ? gl : gh) + i * 16);
        }
    }
    __syncthreads();

    // ---- Layer 2: 64x64x128 ------------------------------------------------
    {
        const int wn2 = wrp & 3;
        float d2[2][2][4];
#pragma unroll
        for (int r = 0; r < 2; r++)
#pragma unroll
            for (int nb = 0; nb < 2; nb++)
#pragma unroll
                for (int c = 0; c < 4; c++) d2[r][nb][c] = 0.f;

        uint32_t a2[2];
#pragma unroll
        for (int r = 0; r < 2; r++)
            a2[r] = smb + (uint32_t)((wm * 32 + r * 16 + (lane & 15)) * 272
                  + (lane >> 4) * 16);
        const uint32_t b2a = smb + W2HI
                  + (uint32_t)((wn2 * 16 + ((lane >> 4) << 3) + (lane & 7)) * 272
                  + ((lane >> 3) & 1) * 16);

#pragma unroll
        for (int ks = 0; ks < 8; ks++) {
            const uint32_t kb = ks * 32;
            uint32_t ah[2][4], al[2][4], bh[4], bl[4];
#pragma unroll
            for (int r = 0; r < 2; r++) {
                LDMX4(ah[r], a2[r] + H1HI + kb);
                LDMX4(al[r], a2[r] + (H1LO - H1HI) + kb);
            }
            LDMX4(bh, b2a + kb);
            LDMX4(bl, b2a + (W2LO - W2HI) + kb);
#pragma unroll
            for (int r = 0; r < 2; r++)
#pragma unroll
                for (int hf = 0; hf < 2; hf++) {
                    MMA_BF16(d2[r][hf], ah[r], bh[hf*2], bh[hf*2+1]);
                    MMA_BF16(d2[r][hf], ah[r], bl[hf*2], bl[hf*2+1]);
                    MMA_BF16(d2[r][hf], al[r], bh[hf*2], bh[hf*2+1]);
                }
        }

        // epilogue 2
#pragma unroll
        for (int r = 0; r < 2; r++) {
            float s_lo = 0.f, s_hi = 0.f;
#pragma unroll
            for (int nb = 0; nb < 2; nb++) {
                const int n = wn2 * 16 + nb * 8 + 2 * (lane & 3);
                s_lo += fmaxf(d2[r][nb][0] + b2s[n], 0.f)     * wouts[n]
                      + fmaxf(d2[r][nb][1] + b2s[n + 1], 0.f) * wouts[n + 1];
                s_hi += fmaxf(d2[r][nb][2] + b2s[n], 0.f)     * wouts[n]
                      + fmaxf(d2[r][nb][3] + b2s[n + 1], 0.f) * wouts[n + 1];
            }
#pragma unroll
            for (int off = 1; off <= 2; off <<= 1) {
                s_lo += __shfl_xor_sync(0xffffffffu, s_lo, off);
                s_hi += __shfl_xor_sync(0xffffffffu, s_hi, off);
            }
            if ((lane & 3) == 0) {
                const int m0 = wm * 32 + r * 16 + (lane >> 2);
                part[wn2][m0]     = s_lo;
                part[wn2][m0 + 8] = s_hi;
            }
        }
    }
    __syncthreads();

    if (t < TILE_R) {
        const int r = rowbase + t;
        if (r < B)
            out[r] = base_s[t] + part[0][t] + part[1][t] + part[2][t] + part[3][t]
                   + bout[0];
    }
}

// ---------------------------------------------------------------------------
extern "C" void kernel_launch(void* const* d_in, const int* in_sizes, int n_in,
                              void* d_out, int out_size)
{
    const int*   uid      = (const int*)  d_in[0];
    const int*   iid      = (const int*)  d_in[1];
    const int*   gen      = (const int*)  d_in[2];
    const int*   age      = (const int*)  d_in[3];
    const int*   occ      = (const int*)  d_in[4];
    const int*   gids     = (const int*)  d_in[5];
    const float* gmask    = (const float*)d_in[6];
    const float* dense    = (const float*)d_in[7];
    const float* fo_user  = (const float*)d_in[8];
    const float* fo_item  = (const float*)d_in[9];
    const float* fo_gender= (const float*)d_in[10];
    const float* fo_age   = (const float*)d_in[11];
    const float* fo_occ   = (const float*)d_in[12];
    const float* fo_genre = (const float*)d_in[13];
    const float* emb_user = (const float*)d_in[14];
    const float* emb_item = (const float*)d_in[15];
    const float* emb_gender=(const float*)d_in[16];
    const float* emb_age  = (const float*)d_in[17];
    const float* emb_occ  = (const float*)d_in[18];
    const float* emb_genre= (const float*)d_in[19];
    const float* dense_W  = (const float*)d_in[20];
    const float* dense_b  = (const float*)d_in[21];
    const float* W1       = (const float*)d_in[22];
    const float* b1       = (const float*)d_in[23];
    const float* W2       = (const float*)d_in[24];
    const float* b2       = (const float*)d_in[25];
    const float* Wout     = (const float*)d_in[26];
    const float* bout     = (const float*)d_in[27];
    float*       out      = (float*)d_out;

    const int B = in_sizes[0];

    // K1: gather (one warp per row) + 96 weight-prep blocks
    {
        const int threads = 256;
        const int rowsPerBlock = threads / 32;
        const int nb1 = (B + rowsPerBlock - 1) / rowsPerBlock;
        deepfm_gather_k1<<<nb1 + 96, threads>>>(
            uid, iid, gen, age, occ, gids, gmask, dense,
            fo_user, fo_item, fo_gender, fo_age, fo_occ, fo_genre,
            emb_user, emb_item, emb_gender, emb_age, emb_occ, emb_genre,
            dense_W, dense_b, W1, W2, B, nb1);
    }
    // K2: HMMA MLP (64 rows/CTA, 2 CTAs/SM, copy-only staging)
    {
        cudaFuncSetAttribute(deepfm_mlp_k2,
                             cudaFuncAttributeMaxDynamicSharedMemorySize, DSM);
        const int blocks = (B + TILE_R - 1) / TILE_R;
        deepfm_mlp_k2<<<blocks, 256, DSM>>>(b1, b2, Wout, bout, out, B);
    }
}

// round 12
// speedup vs baseline: 1.5366x; 1.3030x over previous
#include <cuda_runtime.h>
#include <cuda_bf16.h>
#include <stdint.h>

#define DEEP_IN 200
#define MAXB 16384
#define TILE_R 64
#define XROW 216              // padded X row (elems); 432 B

// ---------------- K2 dynamic smem layout (bytes) ---------------------------
// X   : [64 r][216 k] hi/lo                 0 .. 55296
// WB0 : W1 chunk [128 j][40 k] hi/lo    55296 .. 75776
// WB1 : second buffer                   75776 .. 96256
// h1  (reuses X region): [64][136] hi/lo stride 272
// W2  (reuses WB region): [64][136] hi/lo stride 272
#define XHI    0
#define XLO    27648
#define WB0HI  55296
#define WB1HI  75776
#define WLODEL 10240          // lo half offset within a WB buffer
#define DSM    96256
#define H1HI   0
#define H1LO   17408
#define W2HI   55296
#define W2LO   72704

// pre-split buffers (exact smem layouts)
__device__ __align__(16) __nv_bfloat16 g_xhi[(size_t)MAXB * XROW];
__device__ __align__(16) __nv_bfloat16 g_xlo[(size_t)MAXB * XROW];
__device__ __align__(16) __nv_bfloat16 g_w1chi[7 * 128 * 40];  // [7][128][40], pads zeroed
__device__ __align__(16) __nv_bfloat16 g_w1clo[7 * 128 * 40];
__device__ __align__(16) __nv_bfloat16 g_w2hi[64 * 136];
__device__ __align__(16) __nv_bfloat16 g_w2lo[64 * 136];
__device__ float g_base[MAXB];

__device__ __forceinline__ uint32_t smem_u32(const void* p) {
    uint32_t a;
    asm("{ .reg .u64 t; cvta.to.shared.u64 t, %1; cvt.u32.u64 %0, t; }"
        : "=r"(a) : "l"(p));
    return a;
}
#define LDMX4(r, addr) \
    asm volatile("ldmatrix.sync.aligned.m8n8.x4.shared.b16 {%0,%1,%2,%3}, [%4];" \
        : "=r"((r)[0]), "=r"((r)[1]), "=r"((r)[2]), "=r"((r)[3]) : "r"(addr))
#define MMA_BF16(d, a, b0, b1) \
    asm volatile("mma.sync.aligned.m16n8k16.row.col.f32.bf16.bf16.f32 " \
        "{%0,%1,%2,%3}, {%4,%5,%6,%7}, {%8,%9}, {%0,%1,%2,%3};" \
        : "+f"((d)[0]), "+f"((d)[1]), "+f"((d)[2]), "+f"((d)[3]) \
        : "r"((a)[0]), "r"((a)[1]), "r"((a)[2]), "r"((a)[3]), "r"(b0), "r"(b1))
#define CPA16(dst, src) \
    asm volatile("cp.async.cg.shared.global [%0], [%1], 16;" \
                 :: "r"((uint32_t)(dst)), "l"(src) : "memory")
#define CP_COMMIT() asm volatile("cp.async.commit_group;" ::: "memory")
#define CP_WAIT(n)  asm volatile("cp.async.wait_group %0;" :: "n"(n) : "memory")

__device__ __forceinline__ uint32_t packbf(float v0, float v1) {
    __nv_bfloat162 p = __floats2bfloat162_rn(v0, v1);
    return *(uint32_t*)&p;
}
__device__ __forceinline__ void store_split2(char* hi, char* lo, uint32_t off,
                                             float v0, float v1) {
    __nv_bfloat16 h0 = __float2bfloat16(v0), h1 = __float2bfloat16(v1);
    float l0 = v0 - __bfloat162float(h0), l1 = v1 - __bfloat162float(h1);
    *(uint32_t*)(hi + off) = packbf(__bfloat162float(h0), __bfloat162float(h1));
    *(uint32_t*)(lo + off) = packbf(l0, l1);
}
__device__ __forceinline__ void store_split_g(__nv_bfloat16* ph, __nv_bfloat16* pl,
                                              float x) {
    __nv_bfloat16 h = __float2bfloat16(x);
    *ph = h;
    *pl = __float2bfloat16(x - __bfloat162float(h));
}

// ===========================================================================
// K1: gather + FM terms (one warp per row) + weight pre-split blocks
// ===========================================================================
__global__ void deepfm_gather_k1(
    const int* __restrict__ uid, const int* __restrict__ iid,
    const int* __restrict__ gen, const int* __restrict__ age,
    const int* __restrict__ occ,
    const int* __restrict__ gids, const float* __restrict__ gmask,
    const float* __restrict__ dense,
    const float* __restrict__ fo_user, const float* __restrict__ fo_item,
    const float* __restrict__ fo_gender, const float* __restrict__ fo_age,
    const float* __restrict__ fo_occ, const float* __restrict__ fo_genre,
    const float* __restrict__ emb_user, const float* __restrict__ emb_item,
    const float* __restrict__ emb_gender, const float* __restrict__ emb_age,
    const float* __restrict__ emb_occ, const float* __restrict__ emb_genre,
    const float* __restrict__ dense_W, const float* __restrict__ dense_b,
    const float* __restrict__ W1, const float* __restrict__ W2,
    int B, int nb1)
{
    if ((int)blockIdx.x >= nb1) {
        const int gid = (blockIdx.x - nb1) * blockDim.x + threadIdx.x;
        if (gid < 7 * 128 * 20) {                 // W1 -> [7][128][40]
            const int c = gid / (128 * 20);
            const int rem = gid % (128 * 20);
            const int j = rem / 20, p = rem % 20;
            const int e0 = p * 2;
            float v0 = 0.f, v1 = 0.f;
            if (e0 < 32) {
                const int kg = c * 32 + e0;
                if (kg < DEEP_IN) {
                    const float2 v = *(const float2*)(W1 + j * DEEP_IN + kg);
                    v0 = v.x;
                    if (kg + 1 < DEEP_IN) v1 = v.y;
                }
            }
            const int o = (c * 128 + j) * 40 + e0;
            store_split_g(g_w1chi + o,     g_w1clo + o,     v0);
            store_split_g(g_w1chi + o + 1, g_w1clo + o + 1, v1);
        } else if (gid < 7 * 128 * 20 + 64 * 68) {  // W2 -> [64][136]
            const int idx = gid - 7 * 128 * 20;
            const int j = idx / 68, p = idx % 68;
            const int k = p * 2;
            float v0 = 0.f, v1 = 0.f;
            if (k < 128) {
                const float2 v = *(const float2*)(W2 + j * 128 + k);
                v0 = v.x; v1 = v.y;
            }
            const int o = j * 136 + k;
            store_split_g(g_w2hi + o,     g_w2lo + o,     v0);
            store_split_g(g_w2hi + o + 1, g_w2lo + o + 1, v1);
        }
        return;
    }

    const int r    = (blockIdx.x * blockDim.x + threadIdx.x) >> 5;
    const int lane = threadIdx.x & 31;
    if (r >= B) return;

    const int u  = uid[r];
    const int it = iid[r];
    const int g  = gen[r];
    const int a  = age[r];
    const int o  = occ[r];

    const float xu = emb_user  [u  * 32 + lane];
    const float xi = emb_item  [it * 32 + lane];
    const float xg = emb_gender[g  * 32 + lane];
    const float xa = emb_age   [a  * 32 + lane];
    const float xo = emb_occ   [o  * 32 + lane];

    float gsum = 0.f, msum = 0.f, fsum = 0.f;
#pragma unroll
    for (int k = 0; k < 6; k++) {
        const int   gid = gids [r * 6 + k];
        const float m   = gmask[r * 6 + k];
        gsum += m * emb_genre[gid * 32 + lane];
        msum += m;
        fsum += m * fo_genre[gid];
    }
    const float denom = fmaxf(msum, 1.0f);
    const float xge = gsum / denom;

    __nv_bfloat16* xh = g_xhi + (size_t)r * XROW;
    __nv_bfloat16* xl = g_xlo + (size_t)r * XROW;
    store_split_g(xh + lane,        xl + lane,        xu);
    store_split_g(xh + 32 + lane,   xl + 32 + lane,   xi);
    store_split_g(xh + 64 + lane,   xl + 64 + lane,   xg);
    store_split_g(xh + 96 + lane,   xl + 96 + lane,   xa);
    store_split_g(xh + 128 + lane,  xl + 128 + lane,  xo);
    store_split_g(xh + 160 + lane,  xl + 160 + lane,  xge);
    float dv = 0.f;
    if (lane < 8) {
        dv = dense[r * 8 + lane];
        store_split_g(xh + 192 + lane, xl + 192 + lane, dv);
    }
    if (lane < 16) {   // zero pads k = 200..215
        xh[200 + lane] = __float2bfloat16(0.f);
        xl[200 + lane] = __float2bfloat16(0.f);
    }

    const float s  = xu + xi + xg + xa + xo + xge;
    const float sq = xu*xu + xi*xi + xg*xg + xa*xa + xo*xo + xge*xge;
    float red = 0.5f * (s * s - sq);
    if (lane < 8) red += dv * dense_W[lane];
#pragma unroll
    for (int off = 16; off; off >>= 1)
        red += __shfl_xor_sync(0xffffffffu, red, off);
    if (lane == 0)
        g_base[r] = fo_user[u] + fo_item[it] + fo_gender[g] + fo_age[a]
                  + fo_occ[o] + fsum / denom + dense_b[0] + red;
}

// issue cp.async for W1 chunk c into buffer b (hi+lo, 1280 x 16B)
__device__ __forceinline__ void cpa_chunk(uint32_t smb, int c, int b, int t) {
    const char* gh = (const char*)g_w1chi + c * 10240;
    const char* gl = (const char*)g_w1clo + c * 10240;
    const uint32_t dst = smb + (b ? WB1HI : WB0HI);
    for (int i = t; i < 640; i += 256) {
        CPA16(dst + i * 16,          gh + i * 16);
        CPA16(dst + WLODEL + i * 16, gl + i * 16);
    }
}

// ===========================================================================
// K2: HMMA MLP, 64 rows/CTA, 256 threads, 2 CTAs/SM, cp.async double-buffered
// ===========================================================================
__global__ __launch_bounds__(256, 2) void deepfm_mlp_k2(
    const float* __restrict__ b1, const float* __restrict__ b2,
    const float* __restrict__ Wout, const float* __restrict__ bout,
    float* __restrict__ out, int B)
{
    extern __shared__ char sm[];
    __shared__ float base_s[TILE_R];
    __shared__ float b1s[128], b2s[64], wouts[64];
    __shared__ float part[4][TILE_R];

    const int t    = threadIdx.x;
    const int lane = t & 31;
    const int wrp  = t >> 5;        // 0..7
    const int wm   = wrp >> 2;      // 0..1
    const int rowbase = blockIdx.x * TILE_R;
    const uint32_t smb = smem_u32(sm);

    // ---- prologue: issue all prefetches ------------------------------------
    // group A: X (hi+lo)
    {
        const char* gh = (const char*)g_xhi + (size_t)rowbase * 432;
        const char* gl = (const char*)g_xlo + (size_t)rowbase * 432;
        for (int i = t; i < 1728; i += 256) {
            CPA16(smb + XHI + i * 16, gh + i * 16);
            CPA16(smb + XLO + i * 16, gl + i * 16);
        }
        CP_COMMIT();
    }
    cpa_chunk(smb, 0, 0, t); CP_COMMIT();   // group B: chunk0
    cpa_chunk(smb, 1, 1, t); CP_COMMIT();   // group C: chunk1

    if (t < 128)      b1s[t] = b1[t];
    else if (t < 192) b2s[t - 128] = b2[t - 128];
    else              wouts[t - 192] = Wout[t - 192];
    if (t < TILE_R && rowbase + t < B) base_s[t] = g_base[rowbase + t];

    CP_WAIT(1);          // X + chunk0 landed
    __syncthreads();

    // ---- Layer 1: 64x128x208 over 7 chunks (6x32 + 16 elems) ---------------
    const int wn = wrp & 3;
    float d[2][4][4];
#pragma unroll
    for (int r = 0; r < 2; r++)
#pragma unroll
        for (int nb = 0; nb < 4; nb++)
#pragma unroll
            for (int c = 0; c < 4; c++) d[r][nb][c] = 0.f;

    uint32_t aAddr[2];
#pragma unroll
    for (int r = 0; r < 2; r++)
        aAddr[r] = smb + (uint32_t)((wm * 32 + r * 16 + (lane & 15)) * 432
                 + (lane >> 4) * 16);
    const uint32_t bRow = (uint32_t)((wn * 32 + ((lane >> 4) << 3) + (lane & 7)) * 80
                 + ((lane >> 3) & 1) * 16);
    const uint32_t bRow16 = bRow + 16 * 80;   // h=1 row offset

    for (int c = 0; c < 7; c++) {
        const uint32_t wb = smb + ((c & 1) ? WB1HI : WB0HI);
        const int nks = (c < 6) ? 2 : 1;
        for (int ks = 0; ks < nks; ks++) {
            const uint32_t kbA = c * 64 + ks * 32;
            const uint32_t kbB = ks * 32;
            uint32_t ah[2][4], al[2][4], bh[2][4], bl[2][4];
#pragma unroll
            for (int r = 0; r < 2; r++) {
                LDMX4(ah[r], aAddr[r] + XHI + kbA);
                LDMX4(al[r], aAddr[r] + (XLO - XHI) + kbA);
            }
            LDMX4(bh[0], wb + bRow + kbB);
            LDMX4(bl[0], wb + WLODEL + bRow + kbB);
            LDMX4(bh[1], wb + bRow16 + kbB);
            LDMX4(bl[1], wb + WLODEL + bRow16 + kbB);
#pragma unroll
            for (int r = 0; r < 2; r++)
#pragma unroll
                for (int h = 0; h < 2; h++)
#pragma unroll
                    for (int hf = 0; hf < 2; hf++) {
                        const int nb = h * 2 + hf;
                        MMA_BF16(d[r][nb], ah[r], bh[h][hf*2], bh[h][hf*2+1]);
                        MMA_BF16(d[r][nb], ah[r], bl[h][hf*2], bl[h][hf*2+1]);
                        MMA_BF16(d[r][nb], al[r], bh[h][hf*2], bh[h][hf*2+1]);
                    }
        }
        __syncthreads();                        // buffer reads complete
        if (c + 2 <= 6) { cpa_chunk(smb, c + 2, c & 1, t); CP_COMMIT(); }
        if (c < 6) {
            CP_WAIT(1);                         // chunk c+1 landed
            __syncthreads();
        }
    }

    // ---- issue W2 prefetch (lands during h1 epilogue) ----------------------
    {
        const char* gh = (const char*)g_w2hi;
        const char* gl = (const char*)g_w2lo;
        for (int i = t; i < 1088; i += 256) {
            CPA16(smb + W2HI + i * 16, gh + i * 16);
            CPA16(smb + W2LO + i * 16, gl + i * 16);
        }
        CP_COMMIT();
    }

    // ---- h1 epilogue: relu(d + b1) -> hi/lo [m][k] stride 272 --------------
#pragma unroll
    for (int r = 0; r < 2; r++)
#pragma unroll
        for (int nb = 0; nb < 4; nb++) {
            const int n = wn * 32 + nb * 8 + 2 * (lane & 3);
            const int m0 = wm * 32 + r * 16 + (lane >> 2);
            const float v0 = fmaxf(d[r][nb][0] + b1s[n], 0.f);
            const float v1 = fmaxf(d[r][nb][1] + b1s[n + 1], 0.f);
            store_split2(sm + H1HI, sm + H1LO, m0 * 272 + n * 2, v0, v1);
            const float v2 = fmaxf(d[r][nb][2] + b1s[n], 0.f);
            const float v3 = fmaxf(d[r][nb][3] + b1s[n + 1], 0.f);
            store_split2(sm + H1HI, sm + H1LO, (m0 + 8) * 272 + n * 2, v2, v3);
        }
    CP_WAIT(0);
    __syncthreads();

    // ---- Layer 2: 64x64x128 ------------------------------------------------
    {
        const int wn2 = wrp & 3;
        float d2[2][2][4];
#pragma unroll
        for (int r = 0; r < 2; r++)
#pragma unroll
            for (int nb = 0; nb < 2; nb++)
#pragma unroll
                for (int c = 0; c < 4; c++) d2[r][nb][c] = 0.f;

        uint32_t a2[2];
#pragma unroll
        for (int r = 0; r < 2; r++)
            a2[r] = smb + (uint32_t)((wm * 32 + r * 16 + (lane & 15)) * 272
                  + (lane >> 4) * 16);
        const uint32_t b2a = smb + W2HI
                  + (uint32_t)((wn2 * 16 + ((lane >> 4) << 3) + (lane & 7)) * 272
                  + ((lane >> 3) & 1) * 16);

#pragma unroll
        for (int ks = 0; ks < 8; ks++) {
            const uint32_t kb = ks * 32;
            uint32_t ah[2][4], al[2][4], bh[4], bl[4];
#pragma unroll
            for (int r = 0; r < 2; r++) {
                LDMX4(ah[r], a2[r] + H1HI + kb);
                LDMX4(al[r], a2[r] + (H1LO - H1HI) + kb);
            }
            LDMX4(bh, b2a + kb);
            LDMX4(bl, b2a + (W2LO - W2HI) + kb);
#pragma unroll
            for (int r = 0; r < 2; r++)
#pragma unroll
                for (int hf = 0; hf < 2; hf++) {
                    MMA_BF16(d2[r][hf], ah[r], bh[hf*2], bh[hf*2+1]);
                    MMA_BF16(d2[r][hf], ah[r], bl[hf*2], bl[hf*2+1]);
                    MMA_BF16(d2[r][hf], al[r], bh[hf*2], bh[hf*2+1]);
                }
        }

        // epilogue 2
#pragma unroll
        for (int r = 0; r < 2; r++) {
            float s_lo = 0.f, s_hi = 0.f;
#pragma unroll
            for (int nb = 0; nb < 2; nb++) {
                const int n = wn2 * 16 + nb * 8 + 2 * (lane & 3);
                s_lo += fmaxf(d2[r][nb][0] + b2s[n], 0.f)     * wouts[n]
                      + fmaxf(d2[r][nb][1] + b2s[n + 1], 0.f) * wouts[n + 1];
                s_hi += fmaxf(d2[r][nb][2] + b2s[n], 0.f)     * wouts[n]
                      + fmaxf(d2[r][nb][3] + b2s[n + 1], 0.f) * wouts[n + 1];
            }
#pragma unroll
            for (int off = 1; off <= 2; off <<= 1) {
                s_lo += __shfl_xor_sync(0xffffffffu, s_lo, off);
                s_hi += __shfl_xor_sync(0xffffffffu, s_hi, off);
            }
            if ((lane & 3) == 0) {
                const int m0 = wm * 32 + r * 16 + (lane >> 2);
                part[wn2][m0]     = s_lo;
                part[wn2][m0 + 8] = s_hi;
            }
        }
    }
    __syncthreads();

    if (t < TILE_R) {
        const int r = rowbase + t;
        if (r < B)
            out[r] = base_s[t] + part[0][t] + part[1][t] + part[2][t] + part[3][t]
                   + bout[0];
    }
}

// ---------------------------------------------------------------------------
extern "C" void kernel_launch(void* const* d_in, const int* in_sizes, int n_in,
                              void* d_out, int out_size)
{
    const int*   uid      = (const int*)  d_in[0];
    const int*   iid      = (const int*)  d_in[1];
    const int*   gen      = (const int*)  d_in[2];
    const int*   age      = (const int*)  d_in[3];
    const int*   occ      = (const int*)  d_in[4];
    const int*   gids     = (const int*)  d_in[5];
    const float* gmask    = (const float*)d_in[6];
    const float* dense    = (const float*)d_in[7];
    const float* fo_user  = (const float*)d_in[8];
    const float* fo_item  = (const float*)d_in[9];
    const float* fo_gender= (const float*)d_in[10];
    const float* fo_age   = (const float*)d_in[11];
    const float* fo_occ   = (const float*)d_in[12];
    const float* fo_genre = (const float*)d_in[13];
    const float* emb_user = (const float*)d_in[14];
    const float* emb_item = (const float*)d_in[15];
    const float* emb_gender=(const float*)d_in[16];
    const float* emb_age  = (const float*)d_in[17];
    const float* emb_occ  = (const float*)d_in[18];
    const float* emb_genre= (const float*)d_in[19];
    const float* dense_W  = (const float*)d_in[20];
    const float* dense_b  = (const float*)d_in[21];
    const float* W1       = (const float*)d_in[22];
    const float* b1       = (const float*)d_in[23];
    const float* W2       = (const float*)d_in[24];
    const float* b2       = (const float*)d_in[25];
    const float* Wout     = (const float*)d_in[26];
    const float* bout     = (const float*)d_in[27];
    float*       out      = (float*)d_out;

    const int B = in_sizes[0];

    // K1: gather (one warp per row) + weight-prep blocks
    {
        const int threads = 256;
        const int rowsPerBlock = threads / 32;
        const int nb1 = (B + rowsPerBlock - 1) / rowsPerBlock;
        // prep elems: 7*128*20 (W1) + 64*68 (W2) = 22272 -> 87 blocks
        deepfm_gather_k1<<<nb1 + 90, threads>>>(
            uid, iid, gen, age, occ, gids, gmask, dense,
            fo_user, fo_item, fo_gender, fo_age, fo_occ, fo_genre,
            emb_user, emb_item, emb_gender, emb_age, emb_occ, emb_genre,
            dense_W, dense_b, W1, W2, B, nb1);
    }
    // K2: HMMA MLP (64 rows/CTA, 2 CTAs/SM, cp.async pipeline)
    {
        cudaFuncSetAttribute(deepfm_mlp_k2,
                             cudaFuncAttributeMaxDynamicSharedMemorySize, DSM);
        const int blocks = (B + TILE_R - 1) / TILE_R;
        deepfm_mlp_k2<<<blocks, 256, DSM>>>(b1, b2, Wout, bout, out, B);
    }
}